// round 2
// baseline (speedup 1.0000x reference)
#include <cuda_runtime.h>

// Problem constants (from reference): N=100000, E=1600000, F=128, H=64, L=3
#define NMAX 100000
#define EMAX 1600000

// Scratch (device globals; no allocation allowed)
__device__ float g_agg[NMAX * 128];
__device__ float g_h2[NMAX * 64];
__device__ float g_hA[NMAX * 64];
__device__ float g_hB[NMAX * 64];
__device__ float g_stats[128];   // [0..63] = colsum, [64..127] = colsumsq
__device__ int   g_src[EMAX];
__device__ int   g_dst[EMAX];
__device__ int   g_is32;

// ---------------------------------------------------------------------------
// K0a: reset dtype flag
// ---------------------------------------------------------------------------
__global__ void k_reset_flag() { g_is32 = 0; }

// ---------------------------------------------------------------------------
// K0b: detect edge_index dtype. Scan first 2E int32 words: odd positions are
// all-zero iff the buffer is little-endian int64 node ids (< N).
// ---------------------------------------------------------------------------
__global__ void k_detect(const int* __restrict__ ei, int E) {
    int stride = gridDim.x * blockDim.x;
    for (int j = blockIdx.x * blockDim.x + threadIdx.x; j < E; j += stride) {
        if (ei[2 * j + 1] != 0) { g_is32 = 1; return; }
    }
}

// ---------------------------------------------------------------------------
// K0c: convert edge_index (either dtype) to flat int src/dst arrays
// ---------------------------------------------------------------------------
__global__ void k_convert(const void* __restrict__ ei, int* __restrict__ srcO,
                          int* __restrict__ dstO, int E) {
    int stride = gridDim.x * blockDim.x;
    int is32 = g_is32;
    for (int i = blockIdx.x * blockDim.x + threadIdx.x; i < E; i += stride) {
        if (is32) {
            const int* e = (const int*)ei;
            srcO[i] = e[i];
            dstO[i] = e[E + i];
        } else {
            const long long* e = (const long long*)ei;
            srcO[i] = (int)e[i];
            dstO[i] = (int)e[E + i];
        }
    }
}

// ---------------------------------------------------------------------------
// K1: agg = (1 + eps) * x   (also zero BN stat accumulators)
// ---------------------------------------------------------------------------
__global__ void k_init_agg(const float4* __restrict__ x, const float* __restrict__ epsp,
                           float4* __restrict__ agg, float* __restrict__ stats, int total4) {
    if (blockIdx.x == 0 && threadIdx.x < 128) stats[threadIdx.x] = 0.0f;
    float c = 1.0f + *epsp;
    int stride = gridDim.x * blockDim.x;
    for (int i = blockIdx.x * blockDim.x + threadIdx.x; i < total4; i += stride) {
        float4 v = x[i];
        v.x *= c; v.y *= c; v.z *= c; v.w *= c;
        agg[i] = v;
    }
}

// ---------------------------------------------------------------------------
// K2: edge scatter-add. One warp per edge. agg[dst] += w * x[src]
// ---------------------------------------------------------------------------
template <int F>
__global__ void k_scatter(const float* __restrict__ x, const int* __restrict__ srcA,
                          const int* __restrict__ dstA, const float* __restrict__ ew,
                          float* __restrict__ agg, int E) {
    int gw = (blockIdx.x * blockDim.x + threadIdx.x) >> 5;
    int lane = threadIdx.x & 31;
    if (gw >= E) return;
    int src = srcA[gw];
    int dst = dstA[gw];
    float w = ew[gw];
    if (F == 128) {
        const float4* xr = (const float4*)(x + (size_t)src * 128);
        float4 v = xr[lane];
        float* a = agg + (size_t)dst * 128 + lane * 4;
        atomicAdd(a + 0, v.x * w);
        atomicAdd(a + 1, v.y * w);
        atomicAdd(a + 2, v.z * w);
        atomicAdd(a + 3, v.w * w);
    } else {
        const float2* xr = (const float2*)(x + (size_t)src * 64);
        float2 v = xr[lane];
        float* a = agg + (size_t)dst * 64 + lane * 2;
        atomicAdd(a + 0, v.x * w);
        atomicAdd(a + 1, v.y * w);
    }
}

// ---------------------------------------------------------------------------
// K3: fused MLP: h2 = relu(in @ Wa + ba) @ Wb + bb, + BN batch-stat partials.
// Warp-per-node; each lane produces output columns (lane, lane+32).
// Weights fully SMEM-resident. Dynamic shared memory (FIN=128 needs >48KB).
// ---------------------------------------------------------------------------
template <int FIN>
__global__ __launch_bounds__(256)
void k_mlp(const float* __restrict__ in, const float* __restrict__ Wa,
           const float* __restrict__ ba, const float* __restrict__ Wb,
           const float* __restrict__ bb, float* __restrict__ h2,
           float* __restrict__ stats, int N) {
    extern __shared__ float smem[];
    float* sWa   = smem;                  // FIN*64
    float* sWb   = sWa + FIN * 64;        // 64*64
    float* sba   = sWb + 64 * 64;         // 64
    float* sbb   = sba + 64;              // 64
    float* sxall = sbb + 64;              // 8 * FIN
    float* shall = sxall + 8 * FIN;       // 8 * 64
    float* sstat = shall + 8 * 64;        // 128

    int tid = threadIdx.x;
    for (int i = tid; i < FIN * 64; i += 256) sWa[i] = Wa[i];
    for (int i = tid; i < 64 * 64; i += 256) sWb[i] = Wb[i];
    if (tid < 64) { sba[tid] = ba[tid]; sbb[tid] = bb[tid]; }
    if (tid < 128) sstat[tid] = 0.0f;
    __syncthreads();

    int warp = tid >> 5, lane = tid & 31;
    float* sx = sxall + warp * FIN;
    float* shm = shall + warp * 64;

    float s0 = 0.f, s1 = 0.f, q0 = 0.f, q1 = 0.f;

    for (int n = blockIdx.x * 8 + warp; n < N; n += gridDim.x * 8) {
        const float* xr = in + (size_t)n * FIN;
        #pragma unroll
        for (int r = 0; r < FIN / 32; r++) sx[lane + 32 * r] = xr[lane + 32 * r];
        __syncwarp();

        float a0 = sba[lane], a1 = sba[lane + 32];
        #pragma unroll 8
        for (int k = 0; k < FIN; k++) {
            float xk = sx[k];
            a0 += xk * sWa[k * 64 + lane];
            a1 += xk * sWa[k * 64 + lane + 32];
        }
        a0 = fmaxf(a0, 0.0f);
        a1 = fmaxf(a1, 0.0f);
        shm[lane] = a0; shm[lane + 32] = a1;
        __syncwarp();

        float b0 = sbb[lane], b1 = sbb[lane + 32];
        #pragma unroll 8
        for (int k = 0; k < 64; k++) {
            float hk = shm[k];
            b0 += hk * sWb[k * 64 + lane];
            b1 += hk * sWb[k * 64 + lane + 32];
        }
        h2[(size_t)n * 64 + lane]      = b0;
        h2[(size_t)n * 64 + lane + 32] = b1;
        s0 += b0; q0 += b0 * b0;
        s1 += b1; q1 += b1 * b1;
        __syncwarp();
    }

    atomicAdd(&sstat[lane],      s0);
    atomicAdd(&sstat[lane + 32], s1);
    atomicAdd(&sstat[64 + lane],      q0);
    atomicAdd(&sstat[64 + lane + 32], q1);
    __syncthreads();
    if (tid < 128) atomicAdd(&stats[tid], sstat[tid]);
}

// ---------------------------------------------------------------------------
// K4: BN apply + ReLU + optional residual.  out = [prev +] relu(bn(h2))
// ---------------------------------------------------------------------------
__global__ void k_bn(const float4* __restrict__ h2, const float* __restrict__ stats,
                     const float* __restrict__ g, const float* __restrict__ be,
                     const float4* __restrict__ prev, float4* __restrict__ out,
                     int total4, float invN) {
    __shared__ float sscale[64], sshift[64];
    int tid = threadIdx.x;
    if (tid < 64) {
        float m = stats[tid] * invN;
        float v = stats[64 + tid] * invN - m * m;
        float sc = g[tid] * rsqrtf(v + 1e-5f);
        sscale[tid] = sc;
        sshift[tid] = be[tid] - m * sc;
    }
    __syncthreads();
    int stride = gridDim.x * blockDim.x;
    for (int i = blockIdx.x * blockDim.x + tid; i < total4; i += stride) {
        int c = (i * 4) & 63;
        float4 h = h2[i];
        float4 r;
        r.x = fmaxf(h.x * sscale[c + 0] + sshift[c + 0], 0.0f);
        r.y = fmaxf(h.y * sscale[c + 1] + sshift[c + 1], 0.0f);
        r.z = fmaxf(h.z * sscale[c + 2] + sshift[c + 2], 0.0f);
        r.w = fmaxf(h.w * sscale[c + 3] + sshift[c + 3], 0.0f);
        if (prev) {
            float4 p = prev[i];
            r.x += p.x; r.y += p.y; r.z += p.z; r.w += p.w;
        }
        out[i] = r;
    }
}

// ---------------------------------------------------------------------------
extern "C" void kernel_launch(void* const* d_in, const int* in_sizes, int n_in,
                              void* d_out, int out_size) {
    const float* x    = (const float*)d_in[0];
    const void*  ei   = d_in[1];
    const float* ew   = (const float*)d_in[2];
    const float* eps1 = (const float*)d_in[3];
    const float* W1a  = (const float*)d_in[4];
    const float* b1a  = (const float*)d_in[5];
    const float* W1b  = (const float*)d_in[6];
    const float* b1b  = (const float*)d_in[7];
    const float* g1   = (const float*)d_in[8];
    const float* be1  = (const float*)d_in[9];
    const float* epss = (const float*)d_in[10];
    const float* Wsa  = (const float*)d_in[11];
    const float* bsa  = (const float*)d_in[12];
    const float* Wsb  = (const float*)d_in[13];
    const float* bsb  = (const float*)d_in[14];
    const float* gs   = (const float*)d_in[15];
    const float* bes  = (const float*)d_in[16];

    int N   = in_sizes[0] / 128;
    int E   = in_sizes[2];
    int Lm1 = in_sizes[10];

    float *agg, *h2, *hA, *hB, *stats;
    int *srcA, *dstA;
    cudaGetSymbolAddress((void**)&agg,   g_agg);
    cudaGetSymbolAddress((void**)&h2,    g_h2);
    cudaGetSymbolAddress((void**)&hA,    g_hA);
    cudaGetSymbolAddress((void**)&hB,    g_hB);
    cudaGetSymbolAddress((void**)&stats, g_stats);
    cudaGetSymbolAddress((void**)&srcA,  g_src);
    cudaGetSymbolAddress((void**)&dstA,  g_dst);

    const size_t sh128 = (size_t)(128 * 64 + 64 * 64 + 64 + 64 + 8 * 128 + 8 * 64 + 128) * 4;
    const size_t sh64  = (size_t)(64 * 64 + 64 * 64 + 64 + 64 + 8 * 64 + 8 * 64 + 128) * 4;
    cudaFuncSetAttribute(k_mlp<128>, cudaFuncAttributeMaxDynamicSharedMemorySize, (int)sh128);
    cudaFuncSetAttribute(k_mlp<64>,  cudaFuncAttributeMaxDynamicSharedMemorySize, (int)sh64);

    float invN = 1.0f / (float)N;
    int scatterBlocks = (int)(((long long)E * 32 + 255) / 256);
    int bnBlocks = (N * 16 + 255) / 256;
    int mlpBlocks = 148 * 4;

    // ---- dtype detect + index conversion ----
    k_reset_flag<<<1, 1>>>();
    k_detect<<<512, 256>>>((const int*)ei, E);
    k_convert<<<1024, 256>>>(ei, srcA, dstA, E);

    // ---- layer 1 (F=128 -> H=64) ----
    {
        int t4 = N * 128 / 4;
        k_init_agg<<<(t4 + 255) / 256, 256>>>((const float4*)x, eps1, (float4*)agg, stats, t4);
        k_scatter<128><<<scatterBlocks, 256>>>(x, srcA, dstA, ew, agg, E);
        k_mlp<128><<<mlpBlocks, 256, sh128>>>(agg, W1a, b1a, W1b, b1b, h2, stats, N);
        k_bn<<<bnBlocks, 256>>>((const float4*)h2, stats, g1, be1, nullptr, (float4*)hA,
                                N * 16, invN);
    }

    // ---- layers 2..L (H=64 -> H=64, residual) ----
    const float* cur = hA;
    for (int i = 0; i < Lm1; i++) {
        float* outp = (i == Lm1 - 1) ? (float*)d_out : ((cur == hA) ? hB : hA);
        int t4 = N * 64 / 4;
        k_init_agg<<<(t4 + 255) / 256, 256>>>((const float4*)cur, epss + i, (float4*)agg,
                                              stats, t4);
        k_scatter<64><<<scatterBlocks, 256>>>(cur, srcA, dstA, ew, agg, E);
        k_mlp<64><<<mlpBlocks, 256, sh64>>>(agg, Wsa + (size_t)i * 64 * 64, bsa + i * 64,
                                            Wsb + (size_t)i * 64 * 64, bsb + i * 64,
                                            h2, stats, N);
        k_bn<<<bnBlocks, 256>>>((const float4*)h2, stats, gs + i * 64, bes + i * 64,
                                (const float4*)cur, (float4*)outp, N * 16, invN);
        cur = outp;
    }
}

// round 3
// speedup vs baseline: 1.9637x; 1.9637x over previous
#include <cuda_runtime.h>

// Problem constants (from reference): N=100000, E=1600000, F=128, H=64, L=3
#define NMAX 100000
#define EMAX 1600000

// Scratch (device globals; no allocation allowed)
__device__ float g_h2[NMAX * 64];
__device__ float g_hA[NMAX * 64];
__device__ float g_hB[NMAX * 64];
__device__ float g_stats[128];     // [0..63] colsum, [64..127] colsumsq
__device__ int   g_srcA[EMAX];
__device__ int   g_dstA[EMAX];
__device__ int2  g_edges[EMAX];    // (src, w_bits) grouped by dst
__device__ int   g_deg[NMAX];
__device__ int   g_off[NMAX];
__device__ int   g_cur[NMAX];
__device__ int   g_total;
__device__ int   g_is32;

// ---------------------------------------------------------------------------
// K0a: reset flags + zero degree array
// ---------------------------------------------------------------------------
__global__ void k_prep(int* __restrict__ deg, int N) {
    if (blockIdx.x == 0 && threadIdx.x == 0) { g_total = 0; g_is32 = 0; }
    int stride = gridDim.x * blockDim.x;
    for (int i = blockIdx.x * blockDim.x + threadIdx.x; i < N; i += stride)
        deg[i] = 0;
}

// ---------------------------------------------------------------------------
// K0b: detect edge_index dtype. int64 node ids < N have zero high words.
// ---------------------------------------------------------------------------
__global__ void k_detect(const int* __restrict__ ei, int E) {
    int stride = gridDim.x * blockDim.x;
    for (int j = blockIdx.x * blockDim.x + threadIdx.x; j < E; j += stride) {
        if (ei[2 * j + 1] != 0) { g_is32 = 1; return; }
    }
}

// ---------------------------------------------------------------------------
// K0c: convert indices to int32 and histogram destination degrees
// ---------------------------------------------------------------------------
__global__ void k_convhist(const void* __restrict__ ei, int* __restrict__ srcO,
                           int* __restrict__ dstO, int* __restrict__ deg, int E) {
    int stride = gridDim.x * blockDim.x;
    int is32 = g_is32;
    for (int i = blockIdx.x * blockDim.x + threadIdx.x; i < E; i += stride) {
        int s, d;
        if (is32) {
            const int* e = (const int*)ei;
            s = e[i]; d = e[E + i];
        } else {
            const long long* e = (const long long*)ei;
            s = (int)e[i]; d = (int)e[E + i];
        }
        srcO[i] = s;
        dstO[i] = d;
        atomicAdd(&deg[d], 1);
    }
}

// ---------------------------------------------------------------------------
// K0d: allocate per-node segment offsets (order-free)
// ---------------------------------------------------------------------------
__global__ void k_alloc(const int* __restrict__ deg, int* __restrict__ off,
                        int* __restrict__ cur, int N) {
    int stride = gridDim.x * blockDim.x;
    for (int i = blockIdx.x * blockDim.x + threadIdx.x; i < N; i += stride) {
        int o = atomicAdd(&g_total, deg[i]);
        off[i] = o;
        cur[i] = o;
    }
}

// ---------------------------------------------------------------------------
// K0e: fill CSR edge list (src, weight) grouped by destination
// ---------------------------------------------------------------------------
__global__ void k_fill(const int* __restrict__ srcA, const int* __restrict__ dstA,
                       const float* __restrict__ ew, int* __restrict__ cur,
                       int2* __restrict__ edges, int E) {
    int stride = gridDim.x * blockDim.x;
    for (int i = blockIdx.x * blockDim.x + threadIdx.x; i < E; i += stride) {
        int d = dstA[i];
        int pos = atomicAdd(&cur[d], 1);
        edges[pos] = make_int2(srcA[i], __float_as_int(ew[i]));
    }
}

// ---------------------------------------------------------------------------
// K0f: zero BN stat accumulators
// ---------------------------------------------------------------------------
__global__ void k_zstats(float* __restrict__ stats) { stats[threadIdx.x] = 0.0f; }

// ---------------------------------------------------------------------------
// K1: FUSED per-layer kernel.
//   For each node n (warp-per-node, grid-stride):
//     row = (1+eps) * x[n] + sum_{e in CSR[n]} w_e * x[src_e]   (registers)
//     h2[n] = relu(row @ Wa + ba) @ Wb + bb                      (SMEM weights)
//   plus BN batch-stat partial sums.
// ---------------------------------------------------------------------------
template <int FIN>
__global__ __launch_bounds__(256)
void k_gmlp(const float* __restrict__ x, const int* __restrict__ off,
            const int* __restrict__ deg, const int2* __restrict__ edges,
            const float* __restrict__ epsp,
            const float* __restrict__ Wa, const float* __restrict__ ba,
            const float* __restrict__ Wb, const float* __restrict__ bb,
            float* __restrict__ h2, float* __restrict__ stats, int N) {
    extern __shared__ float smem[];
    float* sWa   = smem;                  // FIN*64
    float* sWb   = sWa + FIN * 64;        // 64*64
    float* sba   = sWb + 64 * 64;         // 64
    float* sbb   = sba + 64;              // 64
    float* sxall = sbb + 64;              // 8 * FIN
    float* shall = sxall + 8 * FIN;       // 8 * 64
    float* sstat = shall + 8 * 64;        // 128

    int tid = threadIdx.x;
    for (int i = tid; i < FIN * 64; i += 256) sWa[i] = Wa[i];
    for (int i = tid; i < 64 * 64; i += 256) sWb[i] = Wb[i];
    if (tid < 64) { sba[tid] = ba[tid]; sbb[tid] = bb[tid]; }
    if (tid < 128) sstat[tid] = 0.0f;
    __syncthreads();

    int warp = tid >> 5, lane = tid & 31;
    float* sx  = sxall + warp * FIN;
    float* shm = shall + warp * 64;
    float c = 1.0f + *epsp;

    float s0 = 0.f, s1 = 0.f, q0 = 0.f, q1 = 0.f;

    for (int n = blockIdx.x * 8 + warp; n < N; n += gridDim.x * 8) {
        int o = off[n];
        int d = deg[n];

        // ---- gather: accumulate weighted neighbor rows in registers ----
        float4 aA, aB;   // aB unused for FIN=64
        if (FIN == 128) {
            const float4* xr = (const float4*)(x + (size_t)n * 128);
            aA = xr[lane];
            aA.x *= c; aA.y *= c; aA.z *= c; aA.w *= c;
        } else {
            const float2* xr = (const float2*)(x + (size_t)n * 64);
            float2 v = xr[lane];
            aA.x = v.x * c; aA.y = v.y * c; aA.z = 0.f; aA.w = 0.f;
        }

        for (int e0 = 0; e0 < d; e0 += 32) {
            int cnt = min(32, d - e0);
            int2 ed = (lane < cnt) ? edges[o + e0 + lane] : make_int2(0, 0);
            int j = 0;
            for (; j + 4 <= cnt; j += 4) {
                int   s_0 = __shfl_sync(0xffffffffu, ed.x, j + 0);
                float w_0 = __int_as_float(__shfl_sync(0xffffffffu, ed.y, j + 0));
                int   s_1 = __shfl_sync(0xffffffffu, ed.x, j + 1);
                float w_1 = __int_as_float(__shfl_sync(0xffffffffu, ed.y, j + 1));
                int   s_2 = __shfl_sync(0xffffffffu, ed.x, j + 2);
                float w_2 = __int_as_float(__shfl_sync(0xffffffffu, ed.y, j + 2));
                int   s_3 = __shfl_sync(0xffffffffu, ed.x, j + 3);
                float w_3 = __int_as_float(__shfl_sync(0xffffffffu, ed.y, j + 3));
                if (FIN == 128) {
                    float4 v0 = ((const float4*)(x + (size_t)s_0 * 128))[lane];
                    float4 v1 = ((const float4*)(x + (size_t)s_1 * 128))[lane];
                    float4 v2 = ((const float4*)(x + (size_t)s_2 * 128))[lane];
                    float4 v3 = ((const float4*)(x + (size_t)s_3 * 128))[lane];
                    aA.x += w_0 * v0.x; aA.y += w_0 * v0.y; aA.z += w_0 * v0.z; aA.w += w_0 * v0.w;
                    aA.x += w_1 * v1.x; aA.y += w_1 * v1.y; aA.z += w_1 * v1.z; aA.w += w_1 * v1.w;
                    aA.x += w_2 * v2.x; aA.y += w_2 * v2.y; aA.z += w_2 * v2.z; aA.w += w_2 * v2.w;
                    aA.x += w_3 * v3.x; aA.y += w_3 * v3.y; aA.z += w_3 * v3.z; aA.w += w_3 * v3.w;
                } else {
                    float2 v0 = ((const float2*)(x + (size_t)s_0 * 64))[lane];
                    float2 v1 = ((const float2*)(x + (size_t)s_1 * 64))[lane];
                    float2 v2 = ((const float2*)(x + (size_t)s_2 * 64))[lane];
                    float2 v3 = ((const float2*)(x + (size_t)s_3 * 64))[lane];
                    aA.x += w_0 * v0.x; aA.y += w_0 * v0.y;
                    aA.x += w_1 * v1.x; aA.y += w_1 * v1.y;
                    aA.x += w_2 * v2.x; aA.y += w_2 * v2.y;
                    aA.x += w_3 * v3.x; aA.y += w_3 * v3.y;
                }
            }
            for (; j < cnt; j++) {
                int   s = __shfl_sync(0xffffffffu, ed.x, j);
                float w = __int_as_float(__shfl_sync(0xffffffffu, ed.y, j));
                if (FIN == 128) {
                    float4 v = ((const float4*)(x + (size_t)s * 128))[lane];
                    aA.x += w * v.x; aA.y += w * v.y; aA.z += w * v.z; aA.w += w * v.w;
                } else {
                    float2 v = ((const float2*)(x + (size_t)s * 64))[lane];
                    aA.x += w * v.x; aA.y += w * v.y;
                }
            }
        }
        (void)aB;

        // ---- stash row in SMEM for the GEMVs ----
        if (FIN == 128) {
            ((float4*)sx)[lane] = aA;
        } else {
            ((float2*)sx)[lane] = make_float2(aA.x, aA.y);
        }
        __syncwarp();

        // ---- MLP layer A: relu(row @ Wa + ba) ----
        float a0 = sba[lane], a1 = sba[lane + 32];
        #pragma unroll 8
        for (int k = 0; k < FIN; k++) {
            float xk = sx[k];
            a0 += xk * sWa[k * 64 + lane];
            a1 += xk * sWa[k * 64 + lane + 32];
        }
        a0 = fmaxf(a0, 0.0f);
        a1 = fmaxf(a1, 0.0f);
        shm[lane] = a0; shm[lane + 32] = a1;
        __syncwarp();

        // ---- MLP layer B: @ Wb + bb ----
        float b0 = sbb[lane], b1 = sbb[lane + 32];
        #pragma unroll 8
        for (int k = 0; k < 64; k++) {
            float hk = shm[k];
            b0 += hk * sWb[k * 64 + lane];
            b1 += hk * sWb[k * 64 + lane + 32];
        }
        h2[(size_t)n * 64 + lane]      = b0;
        h2[(size_t)n * 64 + lane + 32] = b1;
        s0 += b0; q0 += b0 * b0;
        s1 += b1; q1 += b1 * b1;
        __syncwarp();
    }

    atomicAdd(&sstat[lane],           s0);
    atomicAdd(&sstat[lane + 32],      s1);
    atomicAdd(&sstat[64 + lane],      q0);
    atomicAdd(&sstat[64 + lane + 32], q1);
    __syncthreads();
    if (tid < 128) atomicAdd(&stats[tid], sstat[tid]);
}

// ---------------------------------------------------------------------------
// K2: BN apply + ReLU + optional residual.  out = [prev +] relu(bn(h2))
// ---------------------------------------------------------------------------
__global__ void k_bn(const float4* __restrict__ h2, const float* __restrict__ stats,
                     const float* __restrict__ g, const float* __restrict__ be,
                     const float4* __restrict__ prev, float4* __restrict__ out,
                     int total4, float invN) {
    __shared__ float sscale[64], sshift[64];
    int tid = threadIdx.x;
    if (tid < 64) {
        float m = stats[tid] * invN;
        float v = stats[64 + tid] * invN - m * m;
        float sc = g[tid] * rsqrtf(v + 1e-5f);
        sscale[tid] = sc;
        sshift[tid] = be[tid] - m * sc;
    }
    __syncthreads();
    int stride = gridDim.x * blockDim.x;
    for (int i = blockIdx.x * blockDim.x + tid; i < total4; i += stride) {
        int c = (i * 4) & 63;
        float4 h = h2[i];
        float4 r;
        r.x = fmaxf(h.x * sscale[c + 0] + sshift[c + 0], 0.0f);
        r.y = fmaxf(h.y * sscale[c + 1] + sshift[c + 1], 0.0f);
        r.z = fmaxf(h.z * sscale[c + 2] + sshift[c + 2], 0.0f);
        r.w = fmaxf(h.w * sscale[c + 3] + sshift[c + 3], 0.0f);
        if (prev) {
            float4 p = prev[i];
            r.x += p.x; r.y += p.y; r.z += p.z; r.w += p.w;
        }
        out[i] = r;
    }
}

// ---------------------------------------------------------------------------
extern "C" void kernel_launch(void* const* d_in, const int* in_sizes, int n_in,
                              void* d_out, int out_size) {
    const float* x    = (const float*)d_in[0];
    const void*  ei   = d_in[1];
    const float* ew   = (const float*)d_in[2];
    const float* eps1 = (const float*)d_in[3];
    const float* W1a  = (const float*)d_in[4];
    const float* b1a  = (const float*)d_in[5];
    const float* W1b  = (const float*)d_in[6];
    const float* b1b  = (const float*)d_in[7];
    const float* g1   = (const float*)d_in[8];
    const float* be1  = (const float*)d_in[9];
    const float* epss = (const float*)d_in[10];
    const float* Wsa  = (const float*)d_in[11];
    const float* bsa  = (const float*)d_in[12];
    const float* Wsb  = (const float*)d_in[13];
    const float* bsb  = (const float*)d_in[14];
    const float* gs   = (const float*)d_in[15];
    const float* bes  = (const float*)d_in[16];

    int N   = in_sizes[0] / 128;
    int E   = in_sizes[2];
    int Lm1 = in_sizes[10];

    float *h2, *hA, *hB, *stats;
    int *srcA, *dstA, *deg, *off, *cur;
    int2* edges;
    cudaGetSymbolAddress((void**)&h2,    g_h2);
    cudaGetSymbolAddress((void**)&hA,    g_hA);
    cudaGetSymbolAddress((void**)&hB,    g_hB);
    cudaGetSymbolAddress((void**)&stats, g_stats);
    cudaGetSymbolAddress((void**)&srcA,  g_srcA);
    cudaGetSymbolAddress((void**)&dstA,  g_dstA);
    cudaGetSymbolAddress((void**)&deg,   g_deg);
    cudaGetSymbolAddress((void**)&off,   g_off);
    cudaGetSymbolAddress((void**)&cur,   g_cur);
    cudaGetSymbolAddress((void**)&edges, g_edges);

    const size_t sh128 = (size_t)(128 * 64 + 64 * 64 + 64 + 64 + 8 * 128 + 8 * 64 + 128) * 4;
    const size_t sh64  = (size_t)(64 * 64 + 64 * 64 + 64 + 64 + 8 * 64 + 8 * 64 + 128) * 4;
    cudaFuncSetAttribute(k_gmlp<128>, cudaFuncAttributeMaxDynamicSharedMemorySize, (int)sh128);
    cudaFuncSetAttribute(k_gmlp<64>,  cudaFuncAttributeMaxDynamicSharedMemorySize, (int)sh64);

    float invN = 1.0f / (float)N;
    int bnBlocks   = (N * 16 + 255) / 256;
    int gmlpBlocks = 148 * 4;

    // ---- CSR build (by destination) ----
    k_prep<<<(N + 255) / 256, 256>>>(deg, N);
    k_detect<<<512, 256>>>((const int*)ei, E);
    k_convhist<<<1024, 256>>>(ei, srcA, dstA, deg, E);
    k_alloc<<<(N + 255) / 256, 256>>>(deg, off, cur, N);
    k_fill<<<1024, 256>>>(srcA, dstA, ew, cur, edges, E);

    // ---- layer 1 (F=128 -> H=64) ----
    k_zstats<<<1, 128>>>(stats);
    k_gmlp<128><<<gmlpBlocks, 256, sh128>>>(x, off, deg, edges, eps1,
                                            W1a, b1a, W1b, b1b, h2, stats, N);
    k_bn<<<bnBlocks, 256>>>((const float4*)h2, stats, g1, be1, nullptr, (float4*)hA,
                            N * 16, invN);

    // ---- layers 2..L (H=64 -> H=64, residual) ----
    const float* curh = hA;
    for (int i = 0; i < Lm1; i++) {
        float* outp = (i == Lm1 - 1) ? (float*)d_out : ((curh == hA) ? hB : hA);
        k_zstats<<<1, 128>>>(stats);
        k_gmlp<64><<<gmlpBlocks, 256, sh64>>>(curh, off, deg, edges, epss + i,
                                              Wsa + (size_t)i * 64 * 64, bsa + i * 64,
                                              Wsb + (size_t)i * 64 * 64, bsb + i * 64,
                                              h2, stats, N);
        k_bn<<<bnBlocks, 256>>>((const float4*)h2, stats, gs + i * 64, bes + i * 64,
                                (const float4*)curh, (float4*)outp, N * 16, invN);
        curh = outp;
    }
}

// round 4
// speedup vs baseline: 2.6523x; 1.3507x over previous
#include <cuda_runtime.h>

// Problem constants: N=100000, E=1600000, F=128, H=64, L=3
#define NMAX 100000
#define EMAX 1600000

// Scratch (device globals)
__device__ float g_bufY[NMAX * 64];   // y = h@Wa, later reused for h2
__device__ float g_bufZ[NMAX * 64];   // z = relu(agg_y + ba)
__device__ float g_hA[NMAX * 64];
__device__ float g_hB[NMAX * 64];
__device__ float g_stats[128];        // [0..63] colsum, [64..127] colsumsq
__device__ int2  g_edges[EMAX];       // (src, w_bits) grouped by dst
__device__ int   g_deg[NMAX];
__device__ int   g_off[NMAX];
__device__ int   g_cur[NMAX];
__device__ int   g_total;
__device__ int   g_is32;

// ---------------------------------------------------------------------------
// CSR build
// ---------------------------------------------------------------------------
__global__ void k_prep(int* __restrict__ deg, int N) {
    if (blockIdx.x == 0 && threadIdx.x == 0) { g_total = 0; g_is32 = 0; }
    int stride = gridDim.x * blockDim.x;
    for (int i = blockIdx.x * blockDim.x + threadIdx.x; i < N; i += stride)
        deg[i] = 0;
}

__global__ void k_detect(const int* __restrict__ ei, int E) {
    int stride = gridDim.x * blockDim.x;
    for (int j = blockIdx.x * blockDim.x + threadIdx.x; j < E; j += stride) {
        if (ei[2 * j + 1] != 0) { g_is32 = 1; return; }
    }
}

__global__ void k_hist(const void* __restrict__ ei, int* __restrict__ deg, int E) {
    int is32 = g_is32;
    int stride = gridDim.x * blockDim.x;
    for (int i = blockIdx.x * blockDim.x + threadIdx.x; i < E; i += stride) {
        int d = is32 ? ((const int*)ei)[E + i] : (int)((const long long*)ei)[E + i];
        atomicAdd(&deg[d], 1);
    }
}

__global__ void k_alloc(const int* __restrict__ deg, int* __restrict__ off,
                        int* __restrict__ cur, int N) {
    int stride = gridDim.x * blockDim.x;
    for (int i = blockIdx.x * blockDim.x + threadIdx.x; i < N; i += stride) {
        int o = atomicAdd(&g_total, deg[i]);
        off[i] = o;
        cur[i] = o;
    }
}

__global__ void k_fill(const void* __restrict__ ei, const float* __restrict__ ew,
                       int* __restrict__ cur, int2* __restrict__ edges, int E) {
    int is32 = g_is32;
    int stride = gridDim.x * blockDim.x;
    for (int i = blockIdx.x * blockDim.x + threadIdx.x; i < E; i += stride) {
        int s, d;
        if (is32) {
            const int* e = (const int*)ei;
            s = e[i]; d = e[E + i];
        } else {
            const long long* e = (const long long*)ei;
            s = (int)e[i]; d = (int)e[E + i];
        }
        int pos = atomicAdd(&cur[d], 1);
        edges[pos] = make_int2(s, __float_as_int(ew[i]));
    }
}

__global__ void k_zstats(float* __restrict__ stats) { stats[threadIdx.x] = 0.0f; }

// ---------------------------------------------------------------------------
// Tiled dense GEMM: out[N,64] = in[N,FIN] @ W[FIN,64] (+ bias) (+ BN stats)
// Block: 256 threads, tile 64 nodes. Thread tile 4 nodes x 4 cols.
// ---------------------------------------------------------------------------
template <int FIN, bool STATS>
__global__ __launch_bounds__(256)
void k_gemm(const float* __restrict__ in, const float* __restrict__ W,
            const float* __restrict__ bias, float* __restrict__ out,
            float* __restrict__ stats, int N) {
    constexpr int P = FIN + 4;        // padded input row stride (float4-aligned)
    extern __shared__ float sm[];
    float* sW    = sm;                // FIN*64
    float* sIn   = sW + FIN * 64;     // 64*P
    float* sstat = sIn + 64 * P;      // 128

    int tid = threadIdx.x;
    int n0 = blockIdx.x * 64;

    for (int i = tid; i < FIN * 16; i += 256)
        ((float4*)sW)[i] = ((const float4*)W)[i];

    constexpr int KQ = FIN / 4;
    for (int i = tid; i < 64 * KQ; i += 256) {
        int node = i / KQ, kq = i % KQ;
        int row = n0 + node;
        float4 v = (row < N) ? ((const float4*)(in + (size_t)row * FIN))[kq]
                             : make_float4(0.f, 0.f, 0.f, 0.f);
        ((float4*)(sIn + node * P))[kq] = v;
    }
    if (STATS && tid < 128) sstat[tid] = 0.0f;
    __syncthreads();

    int tx = tid & 15, ty = tid >> 4;
    float acc[4][4];
    #pragma unroll
    for (int i = 0; i < 4; i++)
        #pragma unroll
        for (int j = 0; j < 4; j++) acc[i][j] = 0.0f;

    const float* a0p = sIn + (4 * ty + 0) * P;
    const float* a1p = sIn + (4 * ty + 1) * P;
    const float* a2p = sIn + (4 * ty + 2) * P;
    const float* a3p = sIn + (4 * ty + 3) * P;

    #pragma unroll 4
    for (int k = 0; k < FIN; k++) {
        float4 b = *(const float4*)(sW + k * 64 + 4 * tx);
        float a0 = a0p[k], a1 = a1p[k], a2 = a2p[k], a3 = a3p[k];
        acc[0][0] += a0 * b.x; acc[0][1] += a0 * b.y; acc[0][2] += a0 * b.z; acc[0][3] += a0 * b.w;
        acc[1][0] += a1 * b.x; acc[1][1] += a1 * b.y; acc[1][2] += a1 * b.z; acc[1][3] += a1 * b.w;
        acc[2][0] += a2 * b.x; acc[2][1] += a2 * b.y; acc[2][2] += a2 * b.z; acc[2][3] += a2 * b.w;
        acc[3][0] += a3 * b.x; acc[3][1] += a3 * b.y; acc[3][2] += a3 * b.z; acc[3][3] += a3 * b.w;
    }

    float bx = 0.f, by = 0.f, bz = 0.f, bw = 0.f;
    if (bias) {
        float4 bv = *(const float4*)(bias + 4 * tx);
        bx = bv.x; by = bv.y; bz = bv.z; bw = bv.w;
    }

    float s[4] = {0.f, 0.f, 0.f, 0.f};
    float q[4] = {0.f, 0.f, 0.f, 0.f};
    #pragma unroll
    for (int i = 0; i < 4; i++) {
        int row = n0 + 4 * ty + i;
        if (row < N) {
            float4 r = make_float4(acc[i][0] + bx, acc[i][1] + by,
                                   acc[i][2] + bz, acc[i][3] + bw);
            *(float4*)(out + (size_t)row * 64 + 4 * tx) = r;
            if (STATS) {
                s[0] += r.x; q[0] += r.x * r.x;
                s[1] += r.y; q[1] += r.y * r.y;
                s[2] += r.z; q[2] += r.z * r.z;
                s[3] += r.w; q[3] += r.w * r.w;
            }
        }
    }

    if (STATS) {
        #pragma unroll
        for (int j = 0; j < 4; j++) {
            atomicAdd(&sstat[4 * tx + j], s[j]);
            atomicAdd(&sstat[64 + 4 * tx + j], q[j]);
        }
        __syncthreads();
        if (tid < 128) atomicAdd(&stats[tid], sstat[tid]);
    }
}

// ---------------------------------------------------------------------------
// Gather (post-transform): z[n] = relu((1+eps)*y[n] + sum_e w_e*y[src_e] + ba)
// Warp per node; 64-wide rows, float2 per lane, 8-deep edge unroll.
// ---------------------------------------------------------------------------
__global__ __launch_bounds__(256)
void k_gath(const float* __restrict__ y, const int* __restrict__ off,
            const int* __restrict__ deg, const int2* __restrict__ edges,
            const float* __restrict__ epsp, const float* __restrict__ ba,
            float* __restrict__ z, int N) {
    int warp = (blockIdx.x * blockDim.x + threadIdx.x) >> 5;
    int lane = threadIdx.x & 31;
    int nwarps = (gridDim.x * blockDim.x) >> 5;
    float c = 1.0f + *epsp;
    float2 bias = ((const float2*)ba)[lane];

    for (int n = warp; n < N; n += nwarps) {
        int o = off[n];
        int d = deg[n];

        float2 a = ((const float2*)(y + (size_t)n * 64))[lane];
        a.x *= c; a.y *= c;

        for (int e0 = 0; e0 < d; e0 += 32) {
            int cnt = min(32, d - e0);
            int2 ed = (lane < cnt) ? edges[o + e0 + lane] : make_int2(0, 0);
            int j = 0;
            for (; j + 8 <= cnt; j += 8) {
                int si[8]; float wi[8];
                #pragma unroll
                for (int u = 0; u < 8; u++) {
                    si[u] = __shfl_sync(0xffffffffu, ed.x, j + u);
                    wi[u] = __int_as_float(__shfl_sync(0xffffffffu, ed.y, j + u));
                }
                float2 v[8];
                #pragma unroll
                for (int u = 0; u < 8; u++)
                    v[u] = ((const float2*)(y + (size_t)si[u] * 64))[lane];
                #pragma unroll
                for (int u = 0; u < 8; u++) {
                    a.x += wi[u] * v[u].x;
                    a.y += wi[u] * v[u].y;
                }
            }
            for (; j < cnt; j++) {
                int   s = __shfl_sync(0xffffffffu, ed.x, j);
                float w = __int_as_float(__shfl_sync(0xffffffffu, ed.y, j));
                float2 v = ((const float2*)(y + (size_t)s * 64))[lane];
                a.x += w * v.x;
                a.y += w * v.y;
            }
        }

        float2 r = make_float2(fmaxf(a.x + bias.x, 0.0f), fmaxf(a.y + bias.y, 0.0f));
        ((float2*)(z + (size_t)n * 64))[lane] = r;
    }
}

// ---------------------------------------------------------------------------
// BN apply + ReLU + optional residual
// ---------------------------------------------------------------------------
__global__ void k_bn(const float4* __restrict__ h2, const float* __restrict__ stats,
                     const float* __restrict__ g, const float* __restrict__ be,
                     const float4* __restrict__ prev, float4* __restrict__ out,
                     int total4, float invN) {
    __shared__ float sscale[64], sshift[64];
    int tid = threadIdx.x;
    if (tid < 64) {
        float m = stats[tid] * invN;
        float v = stats[64 + tid] * invN - m * m;
        float sc = g[tid] * rsqrtf(v + 1e-5f);
        sscale[tid] = sc;
        sshift[tid] = be[tid] - m * sc;
    }
    __syncthreads();
    int stride = gridDim.x * blockDim.x;
    for (int i = blockIdx.x * blockDim.x + tid; i < total4; i += stride) {
        int c = (i * 4) & 63;
        float4 h = h2[i];
        float4 r;
        r.x = fmaxf(h.x * sscale[c + 0] + sshift[c + 0], 0.0f);
        r.y = fmaxf(h.y * sscale[c + 1] + sshift[c + 1], 0.0f);
        r.z = fmaxf(h.z * sscale[c + 2] + sshift[c + 2], 0.0f);
        r.w = fmaxf(h.w * sscale[c + 3] + sshift[c + 3], 0.0f);
        if (prev) {
            float4 p = prev[i];
            r.x += p.x; r.y += p.y; r.z += p.z; r.w += p.w;
        }
        out[i] = r;
    }
}

// ---------------------------------------------------------------------------
extern "C" void kernel_launch(void* const* d_in, const int* in_sizes, int n_in,
                              void* d_out, int out_size) {
    const float* x    = (const float*)d_in[0];
    const void*  ei   = d_in[1];
    const float* ew   = (const float*)d_in[2];
    const float* eps1 = (const float*)d_in[3];
    const float* W1a  = (const float*)d_in[4];
    const float* b1a  = (const float*)d_in[5];
    const float* W1b  = (const float*)d_in[6];
    const float* b1b  = (const float*)d_in[7];
    const float* g1   = (const float*)d_in[8];
    const float* be1  = (const float*)d_in[9];
    const float* epss = (const float*)d_in[10];
    const float* Wsa  = (const float*)d_in[11];
    const float* bsa  = (const float*)d_in[12];
    const float* Wsb  = (const float*)d_in[13];
    const float* bsb  = (const float*)d_in[14];
    const float* gs   = (const float*)d_in[15];
    const float* bes  = (const float*)d_in[16];

    int N   = in_sizes[0] / 128;
    int E   = in_sizes[2];
    int Lm1 = in_sizes[10];

    float *bufY, *bufZ, *hA, *hB, *stats;
    int *deg, *off, *cur;
    int2* edges;
    cudaGetSymbolAddress((void**)&bufY,  g_bufY);
    cudaGetSymbolAddress((void**)&bufZ,  g_bufZ);
    cudaGetSymbolAddress((void**)&hA,    g_hA);
    cudaGetSymbolAddress((void**)&hB,    g_hB);
    cudaGetSymbolAddress((void**)&stats, g_stats);
    cudaGetSymbolAddress((void**)&deg,   g_deg);
    cudaGetSymbolAddress((void**)&off,   g_off);
    cudaGetSymbolAddress((void**)&cur,   g_cur);
    cudaGetSymbolAddress((void**)&edges, g_edges);

    const size_t shg128 = (size_t)(128 * 64 + 64 * (128 + 4) + 128) * 4;
    const size_t shg64  = (size_t)(64 * 64 + 64 * (64 + 4) + 128) * 4;
    cudaFuncSetAttribute(k_gemm<128, false>, cudaFuncAttributeMaxDynamicSharedMemorySize, (int)shg128);
    cudaFuncSetAttribute(k_gemm<64, false>,  cudaFuncAttributeMaxDynamicSharedMemorySize, (int)shg64);
    cudaFuncSetAttribute(k_gemm<64, true>,   cudaFuncAttributeMaxDynamicSharedMemorySize, (int)shg64);

    float invN = 1.0f / (float)N;
    int gemmBlocks = (N + 63) / 64;
    int gathBlocks = 148 * 8;
    int bnBlocks   = (N * 16 + 255) / 256;

    // ---- CSR build (by destination) ----
    k_prep<<<(N + 255) / 256, 256>>>(deg, N);
    k_detect<<<512, 256>>>((const int*)ei, E);
    k_hist<<<1024, 256>>>(ei, deg, E);
    k_alloc<<<(N + 255) / 256, 256>>>(deg, off, cur, N);
    k_fill<<<1024, 256>>>(ei, ew, cur, edges, E);

    // ---- layer 1 (F=128 -> H=64) ----
    k_gemm<128, false><<<gemmBlocks, 256, shg128>>>(x, W1a, nullptr, bufY, nullptr, N);
    k_gath<<<gathBlocks, 256>>>(bufY, off, deg, edges, eps1, b1a, bufZ, N);
    k_zstats<<<1, 128>>>(stats);
    k_gemm<64, true><<<gemmBlocks, 256, shg64>>>(bufZ, W1b, b1b, bufY, stats, N);
    k_bn<<<bnBlocks, 256>>>((const float4*)bufY, stats, g1, be1, nullptr, (float4*)hA,
                            N * 16, invN);

    // ---- layers 2..L (H=64 -> H=64, residual) ----
    const float* curh = hA;
    for (int i = 0; i < Lm1; i++) {
        float* outp = (i == Lm1 - 1) ? (float*)d_out : ((curh == hA) ? hB : hA);
        k_gemm<64, false><<<gemmBlocks, 256, shg64>>>(curh, Wsa + (size_t)i * 64 * 64,
                                                      nullptr, bufY, nullptr, N);
        k_gath<<<gathBlocks, 256>>>(bufY, off, deg, edges, epss + i, bsa + i * 64,
                                    bufZ, N);
        k_zstats<<<1, 128>>>(stats);
        k_gemm<64, true><<<gemmBlocks, 256, shg64>>>(bufZ, Wsb + (size_t)i * 64 * 64,
                                                     bsb + i * 64, bufY, stats, N);
        k_bn<<<bnBlocks, 256>>>((const float4*)bufY, stats, gs + i * 64, bes + i * 64,
                                (const float4*)curh, (float4*)outp, N * 16, invN);
        curh = outp;
    }
}